// round 9
// baseline (speedup 1.0000x reference)
#include <cuda_runtime.h>
#include <cuda_bf16.h>
#include <cstdint>

// Problem:
//   decoder_states: (32, 512, 1024) f32   d_in[0]
//   encoder_states: (32,1024, 1024) f32   d_in[1]
//   step:           scalar int (unused)   d_in[2]
//   mlp_weight:     (1, 2048) f32         d_in[3]  [0:1024]=w_enc, [1024:2048]=w_dec
//   mlp_bias:       (1,) f32              d_in[4]
//   out[b,t,s] = dot(dec[b,t], w_dec) + dot(enc[b,s], w_enc) + bias

#define DIM        1024
#define BATCH      32
#define T_DEC      512
#define S_ENC      1024
#define N_DEC_ROWS (BATCH * T_DEC)   // 16384
#define N_ENC_ROWS (BATCH * S_ENC)   // 32768
#define RPB 16                       // decoder rows per block in fused kernel

// Kernel A pipeline geometry
#define A_THREADS        128
#define A_ROWS_PER_CHUNK 4                       // 4 rows x 4KB = 16KB per bulk copy
#define A_CHUNKS         4                       // chunks per block
#define A_ROWS_PER_BLOCK (A_ROWS_PER_CHUNK * A_CHUNKS)   // 16
#define A_CHUNK_BYTES    (A_ROWS_PER_CHUNK * DIM * 4)    // 16384

// Scratch (allocation-free rule: __device__ global)
__device__ float g_enc_proj[N_ENC_ROWS];

__device__ __forceinline__ float dot4(const float4 a, const float4 w, float s) {
    s = fmaf(a.x, w.x, s);
    s = fmaf(a.y, w.y, s);
    s = fmaf(a.z, w.z, s);
    return fmaf(a.w, w.w, s);
}

__device__ __forceinline__ uint32_t s2u(const void* p) {
    uint32_t a;
    asm("{ .reg .u64 t; cvta.to.shared.u64 t, %1; cvt.u32.u64 %0, t; }"
        : "=r"(a) : "l"(p));
    return a;
}
__device__ __forceinline__ void mbar_init(uint32_t m, uint32_t cnt) {
    asm volatile("mbarrier.init.shared.b64 [%0], %1;" :: "r"(m), "r"(cnt) : "memory");
}
__device__ __forceinline__ void mbar_expect_tx(uint32_t m, uint32_t bytes) {
    asm volatile("mbarrier.arrive.expect_tx.shared.b64 _, [%0], %1;"
                 :: "r"(m), "r"(bytes) : "memory");
}
__device__ __forceinline__ void mbar_wait(uint32_t m, uint32_t parity) {
    uint32_t done;
    asm volatile("{\n\t.reg .pred p;\n\t"
                 "mbarrier.try_wait.parity.acquire.cta.shared::cta.b64 p, [%1], %2;\n\t"
                 "selp.b32 %0,1,0,p;\n\t}"
                 : "=r"(done) : "r"(m), "r"(parity) : "memory");
    while (!done) {
        asm volatile("{\n\t.reg .pred p;\n\t"
                     "mbarrier.try_wait.parity.acquire.cta.shared::cta.b64 p, [%1], %2, 0x989680;\n\t"
                     "selp.b32 %0,1,0,p;\n\t}"
                     : "=r"(done) : "r"(m), "r"(parity) : "memory");
    }
}
// 1D bulk async copy GMEM -> SMEM (no tensormap needed)
__device__ __forceinline__ void bulk_g2s(uint32_t dst, const void* src,
                                         uint32_t bytes, uint32_t m) {
    asm volatile(
        "cp.async.bulk.shared::cta.global.mbarrier::complete_tx::bytes [%0], [%1], %2, [%3];"
        :: "r"(dst), "l"(src), "r"(bytes), "r"(m) : "memory");
}

// ---------------------------------------------------------------------------
// Kernel A: encoder projection via cp.async.bulk double-buffered pipeline.
// 2048 blocks x 128 threads; block handles 16 rows as 4 chunks of 4 rows.
// One thread issues 16KB bulk copies (async proxy, zero scoreboard pressure);
// 4 warps dot the 4 smem-resident rows with weights held in registers.
// ---------------------------------------------------------------------------
__global__ __launch_bounds__(A_THREADS)
void enc_proj_tma(const float4* __restrict__ enc4,
                  const float4* __restrict__ w4)   // w_enc = mlp_weight[0:1024]
{
    __shared__ alignas(128) float4 buf[2][A_ROWS_PER_CHUNK * (DIM / 4)];
    __shared__ alignas(8) unsigned long long mbar[2];

    const int tid  = threadIdx.x;
    const int w    = tid >> 5;
    const int lane = tid & 31;
    const int base_row = blockIdx.x * A_ROWS_PER_BLOCK;

    const uint32_t m0 = s2u(&mbar[0]), m1 = s2u(&mbar[1]);
    const uint32_t b0 = s2u(&buf[0][0]), b1 = s2u(&buf[1][0]);

    if (tid == 0) { mbar_init(m0, 1); mbar_init(m1, 1); }
    __syncthreads();
    asm volatile("fence.proxy.async.shared::cta;" ::: "memory");

    float4 W[8];
#pragma unroll
    for (int j = 0; j < 8; ++j) W[j] = __ldg(w4 + lane + 32 * j);

    // prologue: chunk 0 -> stage 0
    if (tid == 0) {
        mbar_expect_tx(m0, A_CHUNK_BYTES);
        bulk_g2s(b0, (const char*)enc4 + (size_t)base_row * (DIM * 4),
                 A_CHUNK_BYTES, m0);
    }

#pragma unroll
    for (int c = 0; c < A_CHUNKS; ++c) {
        const int s = c & 1;

        // overlap: issue chunk c+1 into the other stage (consumed & synced at c-1)
        if (tid == 0 && c + 1 < A_CHUNKS) {
            const uint32_t mn = s ? m0 : m1;
            const uint32_t bn = s ? b0 : b1;
            mbar_expect_tx(mn, A_CHUNK_BYTES);
            bulk_g2s(bn,
                     (const char*)enc4 +
                         (size_t)(base_row + (c + 1) * A_ROWS_PER_CHUNK) * (DIM * 4),
                     A_CHUNK_BYTES, mn);
        }

        mbar_wait(s ? m1 : m0, (c >> 1) & 1);   // stage reused every 2 chunks

        // warp w dots smem row w of this chunk
        const float4* __restrict__ r = &buf[s][w * (DIM / 4)];
        float acc = 0.f;
#pragma unroll
        for (int j = 0; j < 8; ++j)
            acc = dot4(r[lane + 32 * j], W[j], acc);
#pragma unroll
        for (int off = 16; off > 0; off >>= 1)
            acc += __shfl_xor_sync(0xFFFFFFFFu, acc, off);

        if (lane == 0)
            g_enc_proj[base_row + c * A_ROWS_PER_CHUNK + w] = acc;
        __syncthreads();   // stage free for reissue at c+1
    }
}

// ---------------------------------------------------------------------------
// Kernel B: fused decoder projection + broadcast write (unchanged from R8).
// ---------------------------------------------------------------------------
__global__ __launch_bounds__(256)
void fused_dec_kernel(const float4* __restrict__ dec4,
                      const float4* __restrict__ w4,    // full mlp_weight
                      const float*  __restrict__ bias,
                      float4* __restrict__ out4)
{
    __shared__ float4 esm[S_ENC / 4];        // 4 KB: enc_proj row for batch b
    __shared__ float  dsm[RPB];

    const int blk  = blockIdx.x;             // 0..1023
    const int b    = blk >> 5;               // 32 chunks of 16 rows per batch
    const int t0   = (blk & 31) * RPB;
    const int tid  = threadIdx.x;
    const int w    = tid >> 5;
    const int lane = tid & 31;

    esm[tid] = __ldg((const float4*)g_enc_proj + b * (S_ENC / 4) + tid);

    const float bi = __ldg(bias);

    const float4* __restrict__ wd = w4 + (DIM / 4);   // w_dec
    float4 W[8];
#pragma unroll
    for (int j = 0; j < 8; ++j) W[j] = __ldg(wd + lane + 32 * j);

    const int row = (b << 9) + t0 + 2 * w;
    const float4* __restrict__ src = dec4 + (size_t)row * (DIM / 4);

    float s0 = 0.f, s1 = 0.f;
#pragma unroll
    for (int j = 0; j < 8; ++j) {
        const int idx = lane + 32 * j;
        const float4 a = __ldcs(src + idx);
        const float4 c = __ldcs(src + 256 + idx);
        s0 = dot4(a, W[j], s0);
        s1 = dot4(c, W[j], s1);
    }
#pragma unroll
    for (int off = 16; off > 0; off >>= 1) {
        s0 += __shfl_xor_sync(0xFFFFFFFFu, s0, off);
        s1 += __shfl_xor_sync(0xFFFFFFFFu, s1, off);
    }
    if (lane == 0) {
        dsm[2 * w]     = s0 + bi;
        dsm[2 * w + 1] = s1 + bi;
    }
    __syncthreads();

    const float4 e = esm[tid];
    float4* __restrict__ obase = out4 + (size_t)((b << 9) + t0) * (DIM / 4) + tid;
#pragma unroll
    for (int r = 0; r < RPB; ++r) {
        const float d = dsm[r];
        float4 o;
        o.x = d + e.x; o.y = d + e.y; o.z = d + e.z; o.w = d + e.w;
        __stcs(obase + (size_t)r * (DIM / 4), o);
    }
}

extern "C" void kernel_launch(void* const* d_in, const int* in_sizes, int n_in,
                              void* d_out, int out_size)
{
    const float4* dec4 = (const float4*)d_in[0];
    const float4* enc4 = (const float4*)d_in[1];
    // d_in[2] = step (unused)
    const float4* w4   = (const float4*)d_in[3];
    const float*  bias = (const float*)d_in[4];
    float4* out4 = (float4*)d_out;

    enc_proj_tma<<<N_ENC_ROWS / A_ROWS_PER_BLOCK, A_THREADS>>>(enc4, w4); // 2048 blocks
    fused_dec_kernel<<<N_DEC_ROWS / RPB, 256>>>(dec4, w4, bias, out4);    // 1024 blocks
}

// round 10
// speedup vs baseline: 1.0255x; 1.0255x over previous
#include <cuda_runtime.h>
#include <cuda_bf16.h>
#include <cstdint>

// Problem:
//   decoder_states: (32, 512, 1024) f32   d_in[0]
//   encoder_states: (32,1024, 1024) f32   d_in[1]
//   step:           scalar int (unused)   d_in[2]
//   mlp_weight:     (1, 2048) f32         d_in[3]  [0:1024]=w_enc, [1024:2048]=w_dec
//   mlp_bias:       (1,) f32              d_in[4]
//   out[b,t,s] = dot(dec[b,t], w_dec) + dot(enc[b,s], w_enc) + bias

#define DIM        1024
#define BATCH      32
#define T_DEC      512
#define S_ENC      1024
#define N_DEC_ROWS (BATCH * T_DEC)   // 16384
#define N_ENC_ROWS (BATCH * S_ENC)   // 32768

// Per batch: 64 producer blocks (16 enc rows each) + 64 consumer blocks (8 dec rows)
#define P_PER_BATCH 64
#define C_PER_BATCH 64
#define BLK_PER_BATCH (P_PER_BATCH + C_PER_BATCH)   // 128
#define GRID (BATCH * BLK_PER_BATCH)                // 4096

// Scratch (allocation-free rule: __device__ globals)
__device__ float g_enc_proj[N_ENC_ROWS];
__device__ int   g_cnt[BATCH];

__device__ __forceinline__ float dot4(const float4 a, const float4 w, float s) {
    s = fmaf(a.x, w.x, s);
    s = fmaf(a.y, w.y, s);
    s = fmaf(a.z, w.z, s);
    return fmaf(a.w, w.w, s);
}

// ---------------------------------------------------------------------------
// Reset: zero the per-batch producer counters. Runs at the head of every
// graph replay, before the merged kernel, so replays are self-consistent.
// ---------------------------------------------------------------------------
__global__ void reset_kernel() {
    if (threadIdx.x < BATCH) g_cnt[threadIdx.x] = 0;
}

// ---------------------------------------------------------------------------
// Merged producer/consumer kernel. Block order interleaves per batch:
//   bid = b*128 + r :  r <  64 -> producer (enc rows b*1024 + r*16 .. +15)
//                      r >= 64 -> consumer (dec rows b*512 + (r-64)*8 .. +7)
// Consumers do their decoder dot FIRST (independent of producers, overlaps
// the enc read stream), then spin on g_cnt[b]==64, then broadcast-store.
// Deadlock-free: consumers wait only on lower-bid producers; producers never
// wait; CTA admission is bid-ordered, so a resident consumer's producers are
// already admitted and will retire.
// ---------------------------------------------------------------------------
__global__ __launch_bounds__(256)
void fused_all(const float4* __restrict__ dec4,
               const float4* __restrict__ enc4,
               const float4* __restrict__ w4,    // full mlp_weight (2048 f32)
               const float*  __restrict__ bias,
               float4* __restrict__ out4)
{
    const int bid  = blockIdx.x;
    const int b    = bid >> 7;            // batch
    const int r    = bid & 127;
    const int tid  = threadIdx.x;
    const int w    = tid >> 5;
    const int lane = tid & 31;

    if (r < P_PER_BATCH) {
        // ---------------- producer: 16 encoder rows, warp-per-2-rows -------
        float4 W[8];
#pragma unroll
        for (int j = 0; j < 8; ++j) W[j] = __ldg(w4 + lane + 32 * j);   // w_enc

        const int row0 = b * S_ENC + r * 16 + 2 * w;
        const float4* __restrict__ src = enc4 + (size_t)row0 * (DIM / 4);

        float s0 = 0.f, s1 = 0.f;
#pragma unroll
        for (int j = 0; j < 8; ++j) {
            const int idx = lane + 32 * j;
            const float4 a = __ldcs(src + idx);
            const float4 c = __ldcs(src + 256 + idx);
            s0 = dot4(a, W[j], s0);
            s1 = dot4(c, W[j], s1);
        }
#pragma unroll
        for (int off = 16; off > 0; off >>= 1) {
            s0 += __shfl_xor_sync(0xFFFFFFFFu, s0, off);
            s1 += __shfl_xor_sync(0xFFFFFFFFu, s1, off);
        }
        if (lane == 0) {
            g_enc_proj[row0]     = s0;
            g_enc_proj[row0 + 1] = s1;
        }
        __syncthreads();                       // all 16 rows written
        if (tid == 0) {
            __threadfence();                   // release enc_proj writes
            atomicAdd(&g_cnt[b], 1);
        }
    } else {
        // ---------------- consumer: 8 decoder rows + broadcast store -------
        __shared__ float4 esm[S_ENC / 4];      // 4 KB enc_proj row of batch b
        __shared__ float  dsm[8];

        const float bi = __ldg(bias);

        float4 W[8];
#pragma unroll
        for (int j = 0; j < 8; ++j) W[j] = __ldg(w4 + (DIM / 4) + lane + 32 * j); // w_dec

        const int t0  = (r - P_PER_BATCH) * 8;
        const int row = b * T_DEC + t0 + w;    // warp w -> row t0+w
        const float4* __restrict__ src = dec4 + (size_t)row * (DIM / 4);

        // decoder dot first: overlaps producers' enc reads
        float acc = 0.f;
#pragma unroll
        for (int j = 0; j < 8; ++j)
            acc = dot4(__ldcs(src + lane + 32 * j), W[j], acc);
#pragma unroll
        for (int off = 16; off > 0; off >>= 1)
            acc += __shfl_xor_sync(0xFFFFFFFFu, acc, off);
        if (lane == 0) dsm[w] = acc + bi;

        // wait for this batch's encoder projections
        if (tid == 0) {
            while (((volatile int*)g_cnt)[b] != P_PER_BATCH) __nanosleep(128);
            __threadfence();                   // acquire
        }
        __syncthreads();

        esm[tid] = ((const float4*)g_enc_proj)[b * (S_ENC / 4) + tid];
        __syncthreads();

        const float4 e = esm[tid];
        float4* __restrict__ obase =
            out4 + (size_t)(b * T_DEC + t0) * (DIM / 4) + tid;
#pragma unroll
        for (int rr = 0; rr < 8; ++rr) {
            const float d = dsm[rr];
            float4 o;
            o.x = d + e.x; o.y = d + e.y; o.z = d + e.z; o.w = d + e.w;
            __stcs(obase + (size_t)rr * (DIM / 4), o);
        }
    }
}

extern "C" void kernel_launch(void* const* d_in, const int* in_sizes, int n_in,
                              void* d_out, int out_size)
{
    const float4* dec4 = (const float4*)d_in[0];
    const float4* enc4 = (const float4*)d_in[1];
    // d_in[2] = step (unused)
    const float4* w4   = (const float4*)d_in[3];
    const float*  bias = (const float*)d_in[4];
    float4* out4 = (float4*)d_out;

    reset_kernel<<<1, 32>>>();
    fused_all<<<GRID, 256>>>(dec4, enc4, w4, bias, out4);
}

// round 11
// speedup vs baseline: 1.0805x; 1.0537x over previous
#include <cuda_runtime.h>
#include <cuda_bf16.h>
#include <cstdint>

// Problem:
//   decoder_states: (32, 512, 1024) f32   d_in[0]
//   encoder_states: (32,1024, 1024) f32   d_in[1]
//   step:           scalar int (unused)   d_in[2]
//   mlp_weight:     (1, 2048) f32         d_in[3]  [0:1024]=w_enc, [1024:2048]=w_dec
//   mlp_bias:       (1,) f32              d_in[4]
//   out[b,t,s] = dot(dec[b,t], w_dec) + dot(enc[b,s], w_enc) + bias

#define DIM        1024
#define BATCH      32
#define T_DEC      512
#define S_ENC      1024
#define N_ENC_ROWS (BATCH * S_ENC)   // 32768

// Per batch: 64 producers (16 enc rows each) + 32 consumers (16 dec rows +
// 16 out rows each). Pre-gate work is 64 KB for BOTH roles -> minimal spin.
#define P_PER_BATCH 64
#define C_PER_BATCH 32
#define BLK_PER_BATCH (P_PER_BATCH + C_PER_BATCH)   // 96
#define GRID (BATCH * BLK_PER_BATCH)                // 3072
#define RPC 16   // rows per consumer

// Scratch (allocation-free rule: __device__ globals).
// Counters are SELF-RESETTING: the last consumer of each batch zeroes both,
// so every graph replay starts from a clean state with no reset kernel.
__device__ float g_enc_proj[N_ENC_ROWS];
__device__ int   g_pcnt[BATCH];   // producers done (zero-initialized)
__device__ int   g_ccnt[BATCH];   // consumers past the gate

__device__ __forceinline__ float dot4(const float4 a, const float4 w, float s) {
    s = fmaf(a.x, w.x, s);
    s = fmaf(a.y, w.y, s);
    s = fmaf(a.z, w.z, s);
    return fmaf(a.w, w.w, s);
}

// ---------------------------------------------------------------------------
// Merged producer/consumer kernel, batch-major block order:
//   bid = b*96 + r :  r <  64 -> producer (enc rows b*1024 + r*16 .. +15)
//                     r >= 64 -> consumer (dec rows b*512 + (r-64)*16 .. +15)
// Consumers compute their decoder dots FIRST (overlapping the enc read
// stream), then gate on g_pcnt[b]==64, then broadcast-store 16 rows.
// Deadlock-free: consumers wait only on lower-bid producers; producers never
// wait; CTA admission is bid-ordered.
// ---------------------------------------------------------------------------
__global__ __launch_bounds__(256)
void fused_all(const float4* __restrict__ dec4,
               const float4* __restrict__ enc4,
               const float4* __restrict__ w4,    // full mlp_weight (2048 f32)
               const float*  __restrict__ bias,
               float4* __restrict__ out4)
{
    const int bid  = blockIdx.x;
    const int b    = bid / BLK_PER_BATCH;
    const int r    = bid - b * BLK_PER_BATCH;
    const int tid  = threadIdx.x;
    const int w    = tid >> 5;
    const int lane = tid & 31;

    if (r < P_PER_BATCH) {
        // ---------------- producer: 16 encoder rows, warp-per-2-rows -------
        float4 W[8];
#pragma unroll
        for (int j = 0; j < 8; ++j) W[j] = __ldg(w4 + lane + 32 * j);   // w_enc

        const int row0 = b * S_ENC + r * 16 + 2 * w;
        const float4* __restrict__ src = enc4 + (size_t)row0 * (DIM / 4);

        float s0 = 0.f, s1 = 0.f;
#pragma unroll
        for (int j = 0; j < 8; ++j) {
            const int idx = lane + 32 * j;
            const float4 a = __ldcs(src + idx);
            const float4 c = __ldcs(src + 256 + idx);
            s0 = dot4(a, W[j], s0);
            s1 = dot4(c, W[j], s1);
        }
#pragma unroll
        for (int off = 16; off > 0; off >>= 1) {
            s0 += __shfl_xor_sync(0xFFFFFFFFu, s0, off);
            s1 += __shfl_xor_sync(0xFFFFFFFFu, s1, off);
        }
        if (lane == 0) {
            g_enc_proj[row0]     = s0;
            g_enc_proj[row0 + 1] = s1;
        }
        __syncthreads();                       // all 16 rows written
        if (tid == 0) {
            __threadfence();                   // release enc_proj writes
            atomicAdd(&g_pcnt[b], 1);
        }
    } else {
        // ------------ consumer: 16 decoder rows + 16 output rows -----------
        __shared__ float4 esm[S_ENC / 4];      // 4 KB enc_proj row of batch b
        __shared__ float  dsm[RPC];

        const float bi = __ldg(bias);

        float4 W[8];
#pragma unroll
        for (int j = 0; j < 8; ++j)
            W[j] = __ldg(w4 + (DIM / 4) + lane + 32 * j);   // w_dec

        const int t0  = (r - P_PER_BATCH) * RPC;
        const int row = b * T_DEC + t0 + 2 * w;   // warp w -> rows t0+2w, +1
        const float4* __restrict__ src = dec4 + (size_t)row * (DIM / 4);

        // decoder dots first: 64 KB pre-gate work, overlaps producer reads
        float s0 = 0.f, s1 = 0.f;
#pragma unroll
        for (int j = 0; j < 8; ++j) {
            const int idx = lane + 32 * j;
            const float4 a = __ldcs(src + idx);
            const float4 c = __ldcs(src + 256 + idx);
            s0 = dot4(a, W[j], s0);
            s1 = dot4(c, W[j], s1);
        }
#pragma unroll
        for (int off = 16; off > 0; off >>= 1) {
            s0 += __shfl_xor_sync(0xFFFFFFFFu, s0, off);
            s1 += __shfl_xor_sync(0xFFFFFFFFu, s1, off);
        }
        if (lane == 0) {
            dsm[2 * w]     = s0 + bi;
            dsm[2 * w + 1] = s1 + bi;
        }

        // gate: wait for this batch's 64 producers
        if (tid == 0) {
            while (((volatile int*)g_pcnt)[b] != P_PER_BATCH) __nanosleep(64);
            __threadfence();                   // acquire
        }
        __syncthreads();

        esm[tid] = ((const float4*)g_enc_proj)[b * (S_ENC / 4) + tid];
        __syncthreads();

        const float4 e = esm[tid];
        float4* __restrict__ obase =
            out4 + (size_t)(b * T_DEC + t0) * (DIM / 4) + tid;
#pragma unroll
        for (int rr = 0; rr < RPC; ++rr) {
            const float d = dsm[rr];
            float4 o;
            o.x = d + e.x; o.y = d + e.y; o.z = d + e.z; o.w = d + e.w;
            __stcs(obase + (size_t)rr * (DIM / 4), o);
        }

        // self-reset: last consumer through the gate zeroes both counters so
        // the next graph replay starts clean (no reset kernel needed).
        if (tid == 0) {
            const int done = atomicAdd(&g_ccnt[b], 1);
            if (done == C_PER_BATCH - 1) {
                g_pcnt[b] = 0;
                g_ccnt[b] = 0;
            }
        }
    }
}

extern "C" void kernel_launch(void* const* d_in, const int* in_sizes, int n_in,
                              void* d_out, int out_size)
{
    const float4* dec4 = (const float4*)d_in[0];
    const float4* enc4 = (const float4*)d_in[1];
    // d_in[2] = step (unused)
    const float4* w4   = (const float4*)d_in[3];
    const float*  bias = (const float*)d_in[4];
    float4* out4 = (float4*)d_out;

    fused_all<<<GRID, 256>>>(dec4, enc4, w4, bias, out4);
}